// round 6
// baseline (speedup 1.0000x reference)
#include <cuda_runtime.h>
#include <cuda_bf16.h>
#include <math.h>
#include <stdint.h>

// ---------------------------------------------------------------------------
// PairwiseAttention round 5: HMMA bf16 hi/lo split everywhere, bf16 hi/lo
// dataflow between kernels (no fp32 intermediate tensors), 512-thread blocks
// (16 warps/SM) for all heavy kernels.
// ---------------------------------------------------------------------------

#define L 256
#define D 128
#define NH 4
#define HD 32
#define M_TOTAL (L * L)          // 65536
#define QKV_N (3 * D)            // 384
#define QSCALE 0.17677669529663687f   // 1/sqrt(32)

// Scratch (__device__ globals; no allocations allowed)
__device__ __nv_bfloat16 g_znh[(size_t)M_TOTAL * D];
__device__ __nv_bfloat16 g_znl[(size_t)M_TOTAL * D];
__device__ __nv_bfloat16 g_qkvh[(size_t)M_TOTAL * QKV_N];
__device__ __nv_bfloat16 g_qkvl[(size_t)M_TOTAL * QKV_N];
__device__ __nv_bfloat16 g_oh[(size_t)M_TOTAL * D];
__device__ __nv_bfloat16 g_ol[(size_t)M_TOTAL * D];
__device__ __nv_bfloat16 g_wqh[D * QKV_N], g_wql[D * QKV_N];
__device__ __nv_bfloat16 g_wph[D * D],     g_wpl[D * D];

// ---- helpers --------------------------------------------------------------
__device__ __forceinline__ uint32_t smem_u32(const void* p) {
    return (uint32_t)__cvta_generic_to_shared(p);
}
__device__ __forceinline__ void ldmx4(uint32_t* r, uint32_t a) {
    asm volatile("ldmatrix.sync.aligned.m8n8.x4.shared.b16 {%0,%1,%2,%3}, [%4];"
                 : "=r"(r[0]), "=r"(r[1]), "=r"(r[2]), "=r"(r[3]) : "r"(a));
}
__device__ __forceinline__ void ldmx4t(uint32_t* r, uint32_t a) {
    asm volatile("ldmatrix.sync.aligned.m8n8.x4.trans.shared.b16 {%0,%1,%2,%3}, [%4];"
                 : "=r"(r[0]), "=r"(r[1]), "=r"(r[2]), "=r"(r[3]) : "r"(a));
}
__device__ __forceinline__ void mma16816(float* d, const uint32_t* a, const uint32_t* b) {
    asm volatile(
        "mma.sync.aligned.m16n8k16.row.col.f32.bf16.bf16.f32 "
        "{%0,%1,%2,%3}, {%4,%5,%6,%7}, {%8,%9}, {%0,%1,%2,%3};"
        : "+f"(d[0]), "+f"(d[1]), "+f"(d[2]), "+f"(d[3])
        : "r"(a[0]), "r"(a[1]), "r"(a[2]), "r"(a[3]), "r"(b[0]), "r"(b[1]));
}
// split v -> hi (bf16) and lo = v - float(hi) (bf16)
__device__ __forceinline__ void split1(float v, __nv_bfloat16& h, __nv_bfloat16& l) {
    h = __float2bfloat16_rn(v);
    l = __float2bfloat16_rn(v - __bfloat162float(h));
}
__device__ __forceinline__ void split4(float4 v, uint2& hi, uint2& lo) {
    __nv_bfloat16 h0, h1, h2, h3, l0, l1, l2, l3;
    split1(v.x, h0, l0); split1(v.y, h1, l1);
    split1(v.z, h2, l2); split1(v.w, h3, l3);
    __nv_bfloat162 a = {h0, h1}, b = {h2, h3}, c = {l0, l1}, d = {l2, l3};
    hi.x = *(uint32_t*)&a; hi.y = *(uint32_t*)&b;
    lo.x = *(uint32_t*)&c; lo.y = *(uint32_t*)&d;
}
// split pair (x,y) -> packed hi uint32 and lo uint32
__device__ __forceinline__ void split2pack(float x, float y, uint32_t& hi, uint32_t& lo) {
    __nv_bfloat16 hx, lx, hy, ly;
    split1(x, hx, lx);
    split1(y, hy, ly);
    __nv_bfloat162 ph = {hx, hy}, pl = {lx, ly};
    hi = *(uint32_t*)&ph;
    lo = *(uint32_t*)&pl;
}

// ---------------------------------------------------------------------------
// LayerNorm -> zn hi/lo bf16. One warp per position.
// ---------------------------------------------------------------------------
__global__ void ln_kernel(const float* __restrict__ z,
                          const float* __restrict__ g,
                          const float* __restrict__ b) {
    int pos  = blockIdx.x * 8 + (threadIdx.x >> 5);
    int lane = threadIdx.x & 31;
    const float* zp = z + (size_t)pos * D;

    float4 v = *(const float4*)&zp[lane * 4];
    float s = v.x + v.y + v.z + v.w;
    #pragma unroll
    for (int o = 16; o; o >>= 1) s += __shfl_xor_sync(0xffffffffu, s, o);
    float mu = s * (1.0f / 128.0f);

    float dx = v.x - mu, dy = v.y - mu, dz = v.z - mu, dw = v.w - mu;
    float q = dx * dx + dy * dy + dz * dz + dw * dw;
    #pragma unroll
    for (int o = 16; o; o >>= 1) q += __shfl_xor_sync(0xffffffffu, q, o);
    float rstd = rsqrtf(q * (1.0f / 128.0f) + 1e-5f);

    float4 gg = *(const float4*)&g[lane * 4];
    float4 bb = *(const float4*)&b[lane * 4];
    float4 o4;
    o4.x = dx * rstd * gg.x + bb.x;
    o4.y = dy * rstd * gg.y + bb.y;
    o4.z = dz * rstd * gg.z + bb.z;
    o4.w = dw * rstd * gg.w + bb.w;

    uint2 hi, lo;
    split4(o4, hi, lo);
    *(uint2*)&g_znh[(size_t)pos * D + lane * 4] = hi;
    *(uint2*)&g_znl[(size_t)pos * D + lane * 4] = lo;
}

// ---------------------------------------------------------------------------
// Split both weight matrices into bf16 hi/lo.
// ---------------------------------------------------------------------------
__global__ void splitw_kernel(const float* __restrict__ wq,
                              const float* __restrict__ wp) {
    int i = blockIdx.x * 256 + threadIdx.x;
    if (i < D * QKV_N) {
        __nv_bfloat16 h, l;
        split1(wq[i], h, l);
        g_wqh[i] = h; g_wql[i] = l;
    } else {
        int j = i - D * QKV_N;
        if (j < D * D) {
            __nv_bfloat16 h, l;
            split1(wp[j], h, l);
            g_wph[j] = h; g_wpl[j] = l;
        }
    }
}

// ---------------------------------------------------------------------------
// GEMM: block tile 128x128, 512 threads (4x4 warps, warp tile 32x32),
// m16n8k16 bf16 x3 hi/lo split. Smem 128 KB (Ah, Al, Bh, Bl swizzled).
// Swizzle: 16B chunk c (0..15) in a 256B row m -> c ^ (m & 7).
// MODE 0: A = g_zn, B = g_wq, C = g_qkv hi/lo bf16 (Q cols pre-scaled)
// MODE 1: A = g_o,  B = g_wp, C = out fp32 (+bias +z residual)
// ---------------------------------------------------------------------------
template<int MODE>
__global__ __launch_bounds__(512, 1)
void gemm_kernel(const float* __restrict__ bias,
                 const float* __restrict__ Zr,
                 float* __restrict__ Cout) {
    constexpr int N = (MODE == 0) ? QKV_N : D;
    extern __shared__ char sm_raw[];
    __nv_bfloat16* Ah = (__nv_bfloat16*)sm_raw;       // 128x128
    __nv_bfloat16* Al = Ah + 128 * 128;
    __nv_bfloat16* Bh = Al + 128 * 128;
    __nv_bfloat16* Bl = Bh + 128 * 128;

    int tid = threadIdx.x;
    int m0 = blockIdx.y * 128;
    int n0 = blockIdx.x * 128;

    const __nv_bfloat16* Ahg = (MODE == 0) ? g_znh : g_oh;   // row width 128
    const __nv_bfloat16* Alg = (MODE == 0) ? g_znl : g_ol;
    const __nv_bfloat16* Bhg = (MODE == 0) ? g_wqh : g_wph;
    const __nv_bfloat16* Blg = (MODE == 0) ? g_wql : g_wpl;

    // ---- stage A (2048 16B chunks per array) ----
    #pragma unroll
    for (int i = 0; i < 4; i++) {
        int idx = tid + i * 512;
        int m = idx >> 4, c = idx & 15;
        int off = m * 128 + ((c ^ (m & 7)) * 8);
        *(uint4*)&Ah[off] = *(const uint4*)&Ahg[(size_t)(m0 + m) * D + c * 8];
        *(uint4*)&Al[off] = *(const uint4*)&Alg[(size_t)(m0 + m) * D + c * 8];
    }
    // ---- stage B ----
    #pragma unroll
    for (int i = 0; i < 4; i++) {
        int idx = tid + i * 512;
        int k = idx >> 4, c = idx & 15;
        int off = k * 128 + ((c ^ (k & 7)) * 8);
        *(uint4*)&Bh[off] = *(const uint4*)&Bhg[(size_t)k * N + n0 + c * 8];
        *(uint4*)&Bl[off] = *(const uint4*)&Blg[(size_t)k * N + n0 + c * 8];
    }
    __syncthreads();

    int w = tid >> 5, l = tid & 31;
    int mw = (w >> 2) * 32, nw = (w & 3) * 32;
    int sel = l >> 3, li = l & 7;

    uint32_t Abase = smem_u32(Ah);
    uint32_t Bbase = smem_u32(Bh);
    const uint32_t LOOFF = 128 * 128 * 2;   // bytes: hi array -> lo array

    float acc[2][4][4];
    #pragma unroll
    for (int mt = 0; mt < 2; mt++)
        #pragma unroll
        for (int nt = 0; nt < 4; nt++)
            #pragma unroll
            for (int j = 0; j < 4; j++) acc[mt][nt][j] = 0.0f;

    #pragma unroll
    for (int kt = 0; kt < 8; kt++) {
        uint32_t af[2][2][4];
        #pragma unroll
        for (int mt = 0; mt < 2; mt++) {
            int m = mw + mt * 16 + li + ((sel & 1) << 3);
            int kc = kt * 2 + (sel >> 1);
            uint32_t ad = Abase + (uint32_t)(m * 128 + ((kc ^ (m & 7)) * 8)) * 2;
            ldmx4(af[0][mt], ad);
            ldmx4(af[1][mt], ad + LOOFF);
        }
        uint32_t bf_[2][4][2];
        #pragma unroll
        for (int p = 0; p < 2; p++) {
            int k = kt * 16 + ((sel & 1) << 3) + li;
            int nc = (nw >> 3) + p * 2 + (sel >> 1);
            uint32_t bd = Bbase + (uint32_t)(k * 128 + ((nc ^ (k & 7)) * 8)) * 2;
            uint32_t t[4];
            ldmx4t(t, bd);
            bf_[0][2 * p][0] = t[0]; bf_[0][2 * p][1] = t[1];
            bf_[0][2 * p + 1][0] = t[2]; bf_[0][2 * p + 1][1] = t[3];
            ldmx4t(t, bd + LOOFF);
            bf_[1][2 * p][0] = t[0]; bf_[1][2 * p][1] = t[1];
            bf_[1][2 * p + 1][0] = t[2]; bf_[1][2 * p + 1][1] = t[3];
        }
        #pragma unroll
        for (int mt = 0; mt < 2; mt++)
            #pragma unroll
            for (int nt = 0; nt < 4; nt++) {
                mma16816(acc[mt][nt], af[0][mt], bf_[0][nt]);
                mma16816(acc[mt][nt], af[0][mt], bf_[1][nt]);
                mma16816(acc[mt][nt], af[1][mt], bf_[0][nt]);
            }
    }

    // ---- epilogue ----
    int grp = l >> 2, qd = l & 3;
    #pragma unroll
    for (int mt = 0; mt < 2; mt++) {
        #pragma unroll
        for (int nt = 0; nt < 4; nt++) {
            int gm = m0 + mw + mt * 16 + grp;
            int gn = n0 + nw + nt * 8 + qd * 2;
            float b0 = bias[gn], b1 = bias[gn + 1];
            float v0 = acc[mt][nt][0] + b0;
            float v1 = acc[mt][nt][1] + b1;
            float v2 = acc[mt][nt][2] + b0;
            float v3 = acc[mt][nt][3] + b1;
            if (MODE == 0) {
                // pre-scale Q columns (gn < 128) by 1/sqrt(hd)
                float sc = (gn < D) ? QSCALE : 1.0f;
                v0 *= sc; v1 *= sc; v2 *= sc; v3 *= sc;
                uint32_t h0, l0, h1, l1;
                split2pack(v0, v1, h0, l0);
                split2pack(v2, v3, h1, l1);
                *(uint32_t*)&g_qkvh[(size_t)gm * N + gn] = h0;
                *(uint32_t*)&g_qkvl[(size_t)gm * N + gn] = l0;
                *(uint32_t*)&g_qkvh[(size_t)(gm + 8) * N + gn] = h1;
                *(uint32_t*)&g_qkvl[(size_t)(gm + 8) * N + gn] = l1;
            } else {
                float2 r0 = *(const float2*)&Zr[(size_t)gm * N + gn];
                float2 r1 = *(const float2*)&Zr[(size_t)(gm + 8) * N + gn];
                *(float2*)&Cout[(size_t)gm * N + gn] =
                    make_float2(v0 + r0.x, v1 + r0.y);
                *(float2*)&Cout[(size_t)(gm + 8) * N + gn] =
                    make_float2(v2 + r1.x, v3 + r1.y);
            }
        }
    }
}

// ---------------------------------------------------------------------------
// Attention: block per (h, r), 512 threads = 16 warps x 16 queries.
// Key tiles of 64, online softmax in C-fragments, P re-split hi/lo in regs.
// smem 96 KB: Q, K, V each [256][64] bf16 (chunks 0-3 hi, 4-7 lo), swizzled.
// ---------------------------------------------------------------------------
__global__ __launch_bounds__(512, 1)
void attn_kernel() {
    extern __shared__ char sm_raw[];
    __nv_bfloat16* Qs = (__nv_bfloat16*)sm_raw;       // 256*64
    __nv_bfloat16* Ks = Qs + 256 * 64;
    __nv_bfloat16* Vs = Ks + 256 * 64;

    int h = blockIdx.x;
    int r = blockIdx.y;
    int tid = threadIdx.x;
    size_t mbase = (size_t)r * L;                     // first position index

    // ---- stage Q, K, V (pure 16B copies; already bf16 hi/lo, Q pre-scaled)
    #pragma unroll
    for (int mat = 0; mat < 3; mat++) {
        __nv_bfloat16* dst = (mat == 0) ? Qs : (mat == 1) ? Ks : Vs;
        int col0 = mat * D + h * HD;
        #pragma unroll
        for (int i = 0; i < 2; i++) {
            int idx = tid + i * 512;               // 1024 (key, chunk) pairs
            int key = idx >> 2, c = idx & 3;
            size_t src = (mbase + key) * QKV_N + col0 + c * 8;
            *(uint4*)&dst[key * 64 + ((c ^ (key & 7)) * 8)] =
                *(const uint4*)&g_qkvh[src];
            *(uint4*)&dst[key * 64 + (((4 + c) ^ (key & 7)) * 8)] =
                *(const uint4*)&g_qkvl[src];
        }
    }
    __syncthreads();

    int w = tid >> 5, l = tid & 31;
    int q0 = w * 16;
    int sel = l >> 3, li = l & 7, grp = l >> 2, qd = l & 3;

    uint32_t Qbase = smem_u32(Qs);
    uint32_t Kbase = smem_u32(Ks);
    uint32_t Vbase = smem_u32(Vs);

    // Q fragments resident: [split][k16-step][4]
    uint32_t qf[2][2][4];
    #pragma unroll
    for (int spl = 0; spl < 2; spl++)
        #pragma unroll
        for (int kk = 0; kk < 2; kk++) {
            int m = q0 + li + ((sel & 1) << 3);
            int kc = spl * 4 + kk * 2 + (sel >> 1);
            ldmx4(qf[spl][kk],
                  Qbase + (uint32_t)(m * 64 + ((kc ^ (m & 7)) * 8)) * 2);
        }

    float mrow[2] = {-1e30f, -1e30f}, lrow[2] = {0.0f, 0.0f};
    float o[4][4];
    #pragma unroll
    for (int nt = 0; nt < 4; nt++)
        #pragma unroll
        for (int j = 0; j < 4; j++) o[nt][j] = 0.0f;

    #pragma unroll 1
    for (int t = 0; t < 4; t++) {
        // ---- S = Q K^T (16 x 64) ----
        float s[8][4];
        #pragma unroll
        for (int nt = 0; nt < 8; nt++)
            #pragma unroll
            for (int j = 0; j < 4; j++) s[nt][j] = 0.0f;

        #pragma unroll
        for (int kk = 0; kk < 2; kk++) {
            uint32_t kf[8][2];
            // K hi fragments
            #pragma unroll
            for (int p = 0; p < 4; p++) {
                int key = t * 64 + p * 16 + ((sel >> 1) << 3) + li;
                int dc = kk * 2 + (sel & 1);
                uint32_t tr[4];
                ldmx4(tr, Kbase + (uint32_t)(key * 64 + ((dc ^ (key & 7)) * 8)) * 2);
                kf[2 * p][0] = tr[0]; kf[2 * p][1] = tr[1];
                kf[2 * p + 1][0] = tr[2]; kf[2 * p + 1][1] = tr[3];
            }
            #pragma unroll
            for (int nt = 0; nt < 8; nt++) {
                mma16816(s[nt], qf[0][kk], kf[nt]);   // hi * hi
                mma16816(s[nt], qf[1][kk], kf[nt]);   // lo * hi
            }
            // K lo fragments (reuse kf regs)
            #pragma unroll
            for (int p = 0; p < 4; p++) {
                int key = t * 64 + p * 16 + ((sel >> 1) << 3) + li;
                int dc = 4 + kk * 2 + (sel & 1);
                uint32_t tr[4];
                ldmx4(tr, Kbase + (uint32_t)(key * 64 + ((dc ^ (key & 7)) * 8)) * 2);
                kf[2 * p][0] = tr[0]; kf[2 * p][1] = tr[1];
                kf[2 * p + 1][0] = tr[2]; kf[2 * p + 1][1] = tr[3];
            }
            #pragma unroll
            for (int nt = 0; nt < 8; nt++)
                mma16816(s[nt], qf[0][kk], kf[nt]);   // hi * lo
        }

        // ---- online softmax ----
        #pragma unroll
        for (int hf = 0; hf < 2; hf++) {
            float tmax = -1e30f;
            #pragma unroll
            for (int nt = 0; nt < 8; nt++) {
                tmax = fmaxf(tmax, s[nt][2 * hf]);
                tmax = fmaxf(tmax, s[nt][2 * hf + 1]);
            }
            tmax = fmaxf(tmax, __shfl_xor_sync(0xffffffffu, tmax, 1));
            tmax = fmaxf(tmax, __shfl_xor_sync(0xffffffffu, tmax, 2));
            float mn = fmaxf(mrow[hf], tmax);
            float corr = __expf(mrow[hf] - mn);
            float ps = 0.0f;
            #pragma unroll
            for (int nt = 0; nt < 8; nt++) {
                float e0 = __expf(s[nt][2 * hf] - mn);
                float e1 = __expf(s[nt][2 * hf + 1] - mn);
                s[nt][2 * hf] = e0;
                s[nt][2 * hf + 1] = e1;
                ps += e0 + e1;
            }
            ps += __shfl_xor_sync(0xffffffffu, ps, 1);
            ps += __shfl_xor_sync(0xffffffffu, ps, 2);
            lrow[hf] = lrow[hf] * corr + ps;
            mrow[hf] = mn;
            #pragma unroll
            for (int nt = 0; nt < 4; nt++) {
                o[nt][2 * hf] *= corr;
                o[nt][2 * hf + 1] *= corr;
            }
        }

        // ---- O += P V ----
        #pragma unroll
        for (int kt = 0; kt < 4; kt++) {
            uint32_t pa[2][4];
            #pragma unroll
            for (int j = 0; j < 4; j++) {
                int nt = 2 * kt + (j >> 1);
                int c0 = (j & 1) * 2;
                split2pack(s[nt][c0], s[nt][c0 + 1], pa[0][j], pa[1][j]);
            }
            uint32_t vf[4][2];
            // V hi fragments
            #pragma unroll
            for (int p = 0; p < 2; p++) {
                int key = t * 64 + kt * 16 + ((sel & 1) << 3) + li;
                int dc = p * 2 + (sel >> 1);
                uint32_t tr[4];
                ldmx4t(tr, Vbase + (uint32_t)(key * 64 + ((dc ^ (key & 7)) * 8)) * 2);
                vf[2 * p][0] = tr[0]; vf[2 * p][1] = tr[1];
                vf[2 * p + 1][0] = tr[2]; vf[2 * p + 1][1] = tr[3];
            }
            #pragma unroll
            for (int nt = 0; nt < 4; nt++) {
                mma16816(o[nt], pa[0], vf[nt]);       // Phi * Vhi
                mma16816(o[nt], pa[1], vf[nt]);       // Plo * Vhi
            }
            // V lo fragments
            #pragma unroll
            for (int p = 0; p < 2; p++) {
                int key = t * 64 + kt * 16 + ((sel & 1) << 3) + li;
                int dc = 4 + p * 2 + (sel >> 1);
                uint32_t tr[4];
                ldmx4t(tr, Vbase + (uint32_t)(key * 64 + ((dc ^ (key & 7)) * 8)) * 2);
                vf[2 * p][0] = tr[0]; vf[2 * p][1] = tr[1];
                vf[2 * p + 1][0] = tr[2]; vf[2 * p + 1][1] = tr[3];
            }
            #pragma unroll
            for (int nt = 0; nt < 4; nt++)
                mma16816(o[nt], pa[0], vf[nt]);       // Phi * Vlo
        }
    }

    // ---- write O as bf16 hi/lo ----
    float inv0 = 1.0f / lrow[0];
    float inv1 = 1.0f / lrow[1];
    #pragma unroll
    for (int nt = 0; nt < 4; nt++) {
        int q = q0 + grp;
        int d = nt * 8 + qd * 2;
        size_t off0 = (mbase + q) * D + h * HD + d;
        size_t off1 = (mbase + q + 8) * D + h * HD + d;
        uint32_t h0, l0, h1, l1;
        split2pack(o[nt][0] * inv0, o[nt][1] * inv0, h0, l0);
        split2pack(o[nt][2] * inv1, o[nt][3] * inv1, h1, l1);
        *(uint32_t*)&g_oh[off0] = h0;
        *(uint32_t*)&g_ol[off0] = l0;
        *(uint32_t*)&g_oh[off1] = h1;
        *(uint32_t*)&g_ol[off1] = l1;
    }
}

// ---------------------------------------------------------------------------
// Launch
// ---------------------------------------------------------------------------
extern "C" void kernel_launch(void* const* d_in, const int* in_sizes, int n_in,
                              void* d_out, int out_size) {
    const float* z      = (const float*)d_in[0];
    const float* ln_g   = (const float*)d_in[1];
    const float* ln_b   = (const float*)d_in[2];
    const float* w_qkv  = (const float*)d_in[3];
    const float* b_qkv  = (const float*)d_in[4];
    const float* w_proj = (const float*)d_in[5];
    const float* b_proj = (const float*)d_in[6];
    float* out = (float*)d_out;

    const int GEMM_SMEM = 4 * 128 * 128 * 2;   // 131072 B
    const int ATTN_SMEM = 3 * 256 * 64 * 2;    //  98304 B
    cudaFuncSetAttribute(gemm_kernel<0>,
                         cudaFuncAttributeMaxDynamicSharedMemorySize, GEMM_SMEM);
    cudaFuncSetAttribute(gemm_kernel<1>,
                         cudaFuncAttributeMaxDynamicSharedMemorySize, GEMM_SMEM);
    cudaFuncSetAttribute(attn_kernel,
                         cudaFuncAttributeMaxDynamicSharedMemorySize, ATTN_SMEM);

    // 1) LN -> zn hi/lo
    ln_kernel<<<M_TOTAL / 8, 256>>>(z, ln_g, ln_b);
    // 2) weight splits (tiny)
    splitw_kernel<<<(D * QKV_N + D * D + 255) / 256, 256>>>(w_qkv, w_proj);
    // 3) QKV GEMM -> bf16 hi/lo (Q pre-scaled)
    gemm_kernel<0><<<dim3(QKV_N / 128, M_TOTAL / 128), 512, GEMM_SMEM>>>(
        b_qkv, nullptr, nullptr);
    // 4) attention -> O bf16 hi/lo
    attn_kernel<<<dim3(NH, L), 512, ATTN_SMEM>>>();
    // 5) proj + bias + residual -> out (fp32)
    gemm_kernel<1><<<dim3(1, M_TOTAL / 128), 512, GEMM_SMEM>>>(
        b_proj, z, out);
}

// round 8
// speedup vs baseline: 1.8978x; 1.8978x over previous
#include <cuda_runtime.h>
#include <cuda_fp16.h>
#include <math.h>
#include <stdint.h>

// ---------------------------------------------------------------------------
// PairwiseAttention round 6: fp16 HMMA. QKV/proj = 2-MMA (single x hi/lo),
// attention = single-pass fp16 (3x fewer MMAs than r4). fp16 dataflow.
// ---------------------------------------------------------------------------

#define L 256
#define D 128
#define NH 4
#define HD 32
#define M_TOTAL (L * L)          // 65536
#define QKV_N (3 * D)            // 384
#define QSCALE 0.17677669529663687f   // 1/sqrt(32)

// Scratch
__device__ __half g_zn[(size_t)M_TOTAL * D];        // 16.8 MB
__device__ __half g_qkv[(size_t)M_TOTAL * QKV_N];   // 50.3 MB (Q pre-scaled)
__device__ __half g_o[(size_t)M_TOTAL * D];         // 16.8 MB
__device__ __half g_wqh[D * QKV_N], g_wql[D * QKV_N];
__device__ __half g_wph[D * D],     g_wpl[D * D];

// ---- helpers --------------------------------------------------------------
__device__ __forceinline__ uint32_t smem_u32(const void* p) {
    return (uint32_t)__cvta_generic_to_shared(p);
}
__device__ __forceinline__ void ldmx4(uint32_t* r, uint32_t a) {
    asm volatile("ldmatrix.sync.aligned.m8n8.x4.shared.b16 {%0,%1,%2,%3}, [%4];"
                 : "=r"(r[0]), "=r"(r[1]), "=r"(r[2]), "=r"(r[3]) : "r"(a));
}
__device__ __forceinline__ void ldmx4t(uint32_t* r, uint32_t a) {
    asm volatile("ldmatrix.sync.aligned.m8n8.x4.trans.shared.b16 {%0,%1,%2,%3}, [%4];"
                 : "=r"(r[0]), "=r"(r[1]), "=r"(r[2]), "=r"(r[3]) : "r"(a));
}
__device__ __forceinline__ void mma16816(float* d, const uint32_t* a, const uint32_t* b) {
    asm volatile(
        "mma.sync.aligned.m16n8k16.row.col.f32.f16.f16.f32 "
        "{%0,%1,%2,%3}, {%4,%5,%6,%7}, {%8,%9}, {%0,%1,%2,%3};"
        : "+f"(d[0]), "+f"(d[1]), "+f"(d[2]), "+f"(d[3])
        : "r"(a[0]), "r"(a[1]), "r"(a[2]), "r"(a[3]), "r"(b[0]), "r"(b[1]));
}
__device__ __forceinline__ uint32_t packh2(float x, float y) {
    __half2 t = __floats2half2_rn(x, y);
    return *(uint32_t*)&t;
}

// ---------------------------------------------------------------------------
// LayerNorm -> zn single fp16. One warp per position.
// ---------------------------------------------------------------------------
__global__ void ln_kernel(const float* __restrict__ z,
                          const float* __restrict__ g,
                          const float* __restrict__ b) {
    int pos  = blockIdx.x * 8 + (threadIdx.x >> 5);
    int lane = threadIdx.x & 31;
    const float* zp = z + (size_t)pos * D;

    float4 v = *(const float4*)&zp[lane * 4];
    float s = v.x + v.y + v.z + v.w;
    #pragma unroll
    for (int o = 16; o; o >>= 1) s += __shfl_xor_sync(0xffffffffu, s, o);
    float mu = s * (1.0f / 128.0f);

    float dx = v.x - mu, dy = v.y - mu, dz = v.z - mu, dw = v.w - mu;
    float q = dx * dx + dy * dy + dz * dz + dw * dw;
    #pragma unroll
    for (int o = 16; o; o >>= 1) q += __shfl_xor_sync(0xffffffffu, q, o);
    float rstd = rsqrtf(q * (1.0f / 128.0f) + 1e-5f);

    float4 gg = *(const float4*)&g[lane * 4];
    float4 bb = *(const float4*)&b[lane * 4];
    uint2 o2;
    o2.x = packh2(dx * rstd * gg.x + bb.x, dy * rstd * gg.y + bb.y);
    o2.y = packh2(dz * rstd * gg.z + bb.z, dw * rstd * gg.w + bb.w);
    *(uint2*)&g_zn[(size_t)pos * D + lane * 4] = o2;
}

// ---------------------------------------------------------------------------
// Split weights into fp16 hi/lo (hi + lo reproduces fp32 to ~2^-22).
// ---------------------------------------------------------------------------
__global__ void splitw_kernel(const float* __restrict__ wq,
                              const float* __restrict__ wp) {
    int i = blockIdx.x * 256 + threadIdx.x;
    if (i < D * QKV_N) {
        float v = wq[i];
        __half h = __float2half_rn(v);
        g_wqh[i] = h;
        g_wql[i] = __float2half_rn(v - __half2float(h));
    } else {
        int j = i - D * QKV_N;
        if (j < D * D) {
            float v = wp[j];
            __half h = __float2half_rn(v);
            g_wph[j] = h;
            g_wpl[j] = __float2half_rn(v - __half2float(h));
        }
    }
}

// ---------------------------------------------------------------------------
// GEMM: C[M x N] = A[M x 128] @ (Wh + Wl)[128 x N], 2 MMAs per tile product.
// Block 128x128, 256 threads, warp grid 2x4, warp tile 64x32 (r4 reuse shape).
// smem 96 KB (A single 32K + Bh 32K + Bl 32K), 2 CTAs/SM.
// Rows = 256B = 16 chunks of 16B, swizzle chunk c -> c ^ (row & 7).
// MODE 0: A=g_zn, B=wq, C=g_qkv fp16 (+bias, Q cols pre-scaled), N=384
// MODE 1: A=g_o,  B=wp, C=out fp32 (+bias +z residual), N=128
// ---------------------------------------------------------------------------
template<int MODE>
__global__ __launch_bounds__(256, 2)
void gemm_kernel(const float* __restrict__ bias,
                 const float* __restrict__ Zr,
                 float* __restrict__ Cout) {
    constexpr int N = (MODE == 0) ? QKV_N : D;
    extern __shared__ char sm_raw[];
    __half* As = (__half*)sm_raw;            // 128x128
    __half* Bh = As + 128 * 128;
    __half* Bl = Bh + 128 * 128;

    int tid = threadIdx.x;
    int m0 = blockIdx.y * 128;
    int n0 = blockIdx.x * 128;

    const __half* Ag  = (MODE == 0) ? g_zn  : g_o;
    const __half* Bhg = (MODE == 0) ? g_wqh : g_wph;
    const __half* Blg = (MODE == 0) ? g_wql : g_wpl;

    // stage A: 128 rows x 16 chunks
    #pragma unroll
    for (int i = 0; i < 8; i++) {
        int idx = tid + i * 256;
        int m = idx >> 4, c = idx & 15;
        *(uint4*)&As[m * 128 + ((c ^ (m & 7)) * 8)] =
            *(const uint4*)&Ag[(size_t)(m0 + m) * D + c * 8];
    }
    // stage B hi/lo
    #pragma unroll
    for (int i = 0; i < 8; i++) {
        int idx = tid + i * 256;
        int k = idx >> 4, c = idx & 15;
        int off = k * 128 + ((c ^ (k & 7)) * 8);
        *(uint4*)&Bh[off] = *(const uint4*)&Bhg[(size_t)k * N + n0 + c * 8];
        *(uint4*)&Bl[off] = *(const uint4*)&Blg[(size_t)k * N + n0 + c * 8];
    }
    __syncthreads();

    int w = tid >> 5, l = tid & 31;
    int mw = (w >> 2) * 64, nw = (w & 3) * 32;
    int sel = l >> 3, li = l & 7;

    uint32_t Abase = smem_u32(As);
    uint32_t Bbase = smem_u32(Bh);
    const uint32_t LOOFF = 128 * 128 * 2;   // Bh -> Bl in bytes

    float acc[4][4][4];
    #pragma unroll
    for (int mt = 0; mt < 4; mt++)
        #pragma unroll
        for (int nt = 0; nt < 4; nt++)
            #pragma unroll
            for (int j = 0; j < 4; j++) acc[mt][nt][j] = 0.0f;

    #pragma unroll
    for (int kt = 0; kt < 8; kt++) {
        uint32_t af[4][4];
        #pragma unroll
        for (int mt = 0; mt < 4; mt++) {
            int m = mw + mt * 16 + li + ((sel & 1) << 3);
            int kc = kt * 2 + (sel >> 1);
            ldmx4(af[mt], Abase + (uint32_t)(m * 128 + ((kc ^ (m & 7)) * 8)) * 2);
        }
        uint32_t bh_[4][2], bl_[4][2];
        #pragma unroll
        for (int p = 0; p < 2; p++) {
            int k = kt * 16 + ((sel & 1) << 3) + li;
            int nc = (nw >> 3) + p * 2 + (sel >> 1);
            uint32_t bd = Bbase + (uint32_t)(k * 128 + ((nc ^ (k & 7)) * 8)) * 2;
            uint32_t t[4];
            ldmx4t(t, bd);
            bh_[2 * p][0] = t[0]; bh_[2 * p][1] = t[1];
            bh_[2 * p + 1][0] = t[2]; bh_[2 * p + 1][1] = t[3];
            ldmx4t(t, bd + LOOFF);
            bl_[2 * p][0] = t[0]; bl_[2 * p][1] = t[1];
            bl_[2 * p + 1][0] = t[2]; bl_[2 * p + 1][1] = t[3];
        }
        #pragma unroll
        for (int mt = 0; mt < 4; mt++)
            #pragma unroll
            for (int nt = 0; nt < 4; nt++) {
                mma16816(acc[mt][nt], af[mt], bh_[nt]);
                mma16816(acc[mt][nt], af[mt], bl_[nt]);
            }
    }

    // epilogue
    int grp = l >> 2, qd = l & 3;
    #pragma unroll
    for (int mt = 0; mt < 4; mt++) {
        #pragma unroll
        for (int nt = 0; nt < 4; nt++) {
            int gm = m0 + mw + mt * 16 + grp;
            int gn = n0 + nw + nt * 8 + qd * 2;
            float b0 = bias[gn], b1 = bias[gn + 1];
            float v0 = acc[mt][nt][0] + b0;
            float v1 = acc[mt][nt][1] + b1;
            float v2 = acc[mt][nt][2] + b0;
            float v3 = acc[mt][nt][3] + b1;
            if (MODE == 0) {
                float sc = (gn < D) ? QSCALE : 1.0f;
                *(uint32_t*)&g_qkv[(size_t)gm * N + gn] = packh2(v0 * sc, v1 * sc);
                *(uint32_t*)&g_qkv[(size_t)(gm + 8) * N + gn] = packh2(v2 * sc, v3 * sc);
            } else {
                float2 r0 = *(const float2*)&Zr[(size_t)gm * N + gn];
                float2 r1 = *(const float2*)&Zr[(size_t)(gm + 8) * N + gn];
                *(float2*)&Cout[(size_t)gm * N + gn] = make_float2(v0 + r0.x, v1 + r0.y);
                *(float2*)&Cout[(size_t)(gm + 8) * N + gn] = make_float2(v2 + r1.x, v3 + r1.y);
            }
        }
    }
}

// ---------------------------------------------------------------------------
// Attention: block per (h, r), 256 threads = 8 warps x 32 queries.
// Single-pass fp16 MMAs, key tiles of 32, online softmax.
// smem: Q/K/V each [256][pitch 40 halves] (80B rows -> bank-conflict-free,
// no swizzle). 60 KB total, 2 CTAs/SM.
// ---------------------------------------------------------------------------
#define APITCH 40
__global__ __launch_bounds__(256, 2)
void attn_kernel() {
    extern __shared__ char sm_raw[];
    __half* Qs = (__half*)sm_raw;            // 256 * 40
    __half* Ks = Qs + 256 * APITCH;
    __half* Vs = Ks + 256 * APITCH;

    int h = blockIdx.x;
    int r = blockIdx.y;
    int tid = threadIdx.x;
    size_t mbase = (size_t)r * L;

    // stage Q, K, V: 256 pos x 4 chunks of 16B each, per matrix
    #pragma unroll
    for (int mat = 0; mat < 3; mat++) {
        __half* dst = (mat == 0) ? Qs : (mat == 1) ? Ks : Vs;
        int col0 = mat * D + h * HD;
        #pragma unroll
        for (int i = 0; i < 4; i++) {
            int idx = tid + i * 256;          // 1024 (pos, chunk)
            int pos = idx >> 2, c = idx & 3;
            *(uint4*)&dst[pos * APITCH + c * 8] =
                *(const uint4*)&g_qkv[(mbase + pos) * QKV_N + col0 + c * 8];
        }
    }
    __syncthreads();

    int w = tid >> 5, l = tid & 31;
    int q0 = w * 32;
    int sel = l >> 3, li = l & 7, grp = l >> 2, qd = l & 3;

    uint32_t Qbase = smem_u32(Qs);
    uint32_t Kbase = smem_u32(Ks);
    uint32_t Vbase = smem_u32(Vs);

    // Q fragments resident: [kk(2)][mt(2)][4]
    uint32_t qf[2][2][4];
    #pragma unroll
    for (int kk = 0; kk < 2; kk++)
        #pragma unroll
        for (int mt = 0; mt < 2; mt++) {
            int m = q0 + mt * 16 + li + ((sel & 1) << 3);
            int kc = kk * 2 + (sel >> 1);
            ldmx4(qf[kk][mt], Qbase + (uint32_t)(m * APITCH + kc * 8) * 2);
        }

    float mrow[2][2], lrow[2][2];
    float o[2][4][4];
    #pragma unroll
    for (int mt = 0; mt < 2; mt++) {
        #pragma unroll
        for (int hf = 0; hf < 2; hf++) { mrow[mt][hf] = -1e30f; lrow[mt][hf] = 0.0f; }
        #pragma unroll
        for (int nt = 0; nt < 4; nt++)
            #pragma unroll
            for (int j = 0; j < 4; j++) o[mt][nt][j] = 0.0f;
    }

    #pragma unroll 1
    for (int t = 0; t < 8; t++) {             // key tiles of 32
        // ---- S = Q K^T (32 x 32) ----
        float s[2][4][4];
        #pragma unroll
        for (int mt = 0; mt < 2; mt++)
            #pragma unroll
            for (int nt = 0; nt < 4; nt++)
                #pragma unroll
                for (int j = 0; j < 4; j++) s[mt][nt][j] = 0.0f;

        #pragma unroll
        for (int kk = 0; kk < 2; kk++) {
            uint32_t kf[4][2];
            #pragma unroll
            for (int p = 0; p < 2; p++) {
                int key = t * 32 + p * 16 + ((sel >> 1) << 3) + li;
                int dc = kk * 2 + (sel & 1);
                uint32_t tr[4];
                ldmx4(tr, Kbase + (uint32_t)(key * APITCH + dc * 8) * 2);
                kf[2 * p][0] = tr[0]; kf[2 * p][1] = tr[1];
                kf[2 * p + 1][0] = tr[2]; kf[2 * p + 1][1] = tr[3];
            }
            #pragma unroll
            for (int mt = 0; mt < 2; mt++)
                #pragma unroll
                for (int nt = 0; nt < 4; nt++)
                    mma16816(s[mt][nt], qf[kk][mt], kf[nt]);
        }

        // ---- online softmax ----
        #pragma unroll
        for (int mt = 0; mt < 2; mt++)
            #pragma unroll
            for (int hf = 0; hf < 2; hf++) {
                float tmax = -1e30f;
                #pragma unroll
                for (int nt = 0; nt < 4; nt++) {
                    tmax = fmaxf(tmax, s[mt][nt][2 * hf]);
                    tmax = fmaxf(tmax, s[mt][nt][2 * hf + 1]);
                }
                tmax = fmaxf(tmax, __shfl_xor_sync(0xffffffffu, tmax, 1));
                tmax = fmaxf(tmax, __shfl_xor_sync(0xffffffffu, tmax, 2));
                float mn = fmaxf(mrow[mt][hf], tmax);
                float corr = __expf(mrow[mt][hf] - mn);
                float ps = 0.0f;
                #pragma unroll
                for (int nt = 0; nt < 4; nt++) {
                    float e0 = __expf(s[mt][nt][2 * hf] - mn);
                    float e1 = __expf(s[mt][nt][2 * hf + 1] - mn);
                    s[mt][nt][2 * hf] = e0;
                    s[mt][nt][2 * hf + 1] = e1;
                    ps += e0 + e1;
                }
                ps += __shfl_xor_sync(0xffffffffu, ps, 1);
                ps += __shfl_xor_sync(0xffffffffu, ps, 2);
                lrow[mt][hf] = lrow[mt][hf] * corr + ps;
                mrow[mt][hf] = mn;
                #pragma unroll
                for (int nt = 0; nt < 4; nt++) {
                    o[mt][nt][2 * hf] *= corr;
                    o[mt][nt][2 * hf + 1] *= corr;
                }
            }

        // ---- O += P V ----
        #pragma unroll
        for (int kt = 0; kt < 2; kt++) {      // k16 steps over 32 keys
            uint32_t pa[2][4];
            #pragma unroll
            for (int mt = 0; mt < 2; mt++)
                #pragma unroll
                for (int j = 0; j < 4; j++) {
                    int nt = 2 * kt + (j >> 1);
                    int c0 = (j & 1) * 2;
                    pa[mt][j] = packh2(s[mt][nt][c0], s[mt][nt][c0 + 1]);
                }
            uint32_t vf[4][2];
            #pragma unroll
            for (int p = 0; p < 2; p++) {
                int key = t * 32 + kt * 16 + ((sel & 1) << 3) + li;
                int dc = p * 2 + (sel >> 1);
                uint32_t tr[4];
                ldmx4t(tr, Vbase + (uint32_t)(key * APITCH + dc * 8) * 2);
                vf[2 * p][0] = tr[0]; vf[2 * p][1] = tr[1];
                vf[2 * p + 1][0] = tr[2]; vf[2 * p + 1][1] = tr[3];
            }
            #pragma unroll
            for (int mt = 0; mt < 2; mt++)
                #pragma unroll
                for (int nt = 0; nt < 4; nt++)
                    mma16816(o[mt][nt], pa[mt], vf[nt]);
        }
    }

    // ---- write O as single fp16 ----
    #pragma unroll
    for (int mt = 0; mt < 2; mt++) {
        float inv0 = 1.0f / lrow[mt][0];
        float inv1 = 1.0f / lrow[mt][1];
        #pragma unroll
        for (int nt = 0; nt < 4; nt++) {
            int q = q0 + mt * 16 + grp;
            int d = nt * 8 + qd * 2;
            size_t off0 = (mbase + q) * D + h * HD + d;
            size_t off1 = (mbase + q + 8) * D + h * HD + d;
            *(uint32_t*)&g_o[off0] = packh2(o[mt][nt][0] * inv0, o[mt][nt][1] * inv0);
            *(uint32_t*)&g_o[off1] = packh2(o[mt][nt][2] * inv1, o[mt][nt][3] * inv1);
        }
    }
}

// ---------------------------------------------------------------------------
// Launch
// ---------------------------------------------------------------------------
extern "C" void kernel_launch(void* const* d_in, const int* in_sizes, int n_in,
                              void* d_out, int out_size) {
    const float* z      = (const float*)d_in[0];
    const float* ln_g   = (const float*)d_in[1];
    const float* ln_b   = (const float*)d_in[2];
    const float* w_qkv  = (const float*)d_in[3];
    const float* b_qkv  = (const float*)d_in[4];
    const float* w_proj = (const float*)d_in[5];
    const float* b_proj = (const float*)d_in[6];
    float* out = (float*)d_out;

    const int GEMM_SMEM = 3 * 128 * 128 * 2;       //  98304 B
    const int ATTN_SMEM = 3 * 256 * APITCH * 2;    //  61440 B
    cudaFuncSetAttribute(gemm_kernel<0>,
                         cudaFuncAttributeMaxDynamicSharedMemorySize, GEMM_SMEM);
    cudaFuncSetAttribute(gemm_kernel<1>,
                         cudaFuncAttributeMaxDynamicSharedMemorySize, GEMM_SMEM);
    cudaFuncSetAttribute(attn_kernel,
                         cudaFuncAttributeMaxDynamicSharedMemorySize, ATTN_SMEM);

    // 1) LN -> zn fp16
    ln_kernel<<<M_TOTAL / 8, 256>>>(z, ln_g, ln_b);
    // 2) weight splits (tiny)
    splitw_kernel<<<(D * QKV_N + D * D + 255) / 256, 256>>>(w_qkv, w_proj);
    // 3) QKV GEMM -> fp16 (Q pre-scaled)
    gemm_kernel<0><<<dim3(QKV_N / 128, M_TOTAL / 128), 256, GEMM_SMEM>>>(
        b_qkv, nullptr, nullptr);
    // 4) attention -> O fp16
    attn_kernel<<<dim3(NH, L), 256, ATTN_SMEM>>>();
    // 5) proj + bias + residual -> out (fp32)
    gemm_kernel<1><<<dim3(1, M_TOTAL / 128), 256, GEMM_SMEM>>>(
        b_proj, z, out);
}

// round 9
// speedup vs baseline: 2.4741x; 1.3037x over previous
#include <cuda_runtime.h>
#include <cuda_fp16.h>
#include <math.h>
#include <stdint.h>

// ---------------------------------------------------------------------------
// PairwiseAttention round 7: fp16 HMMA single-pass GEMMs; attention with
// offset-softmax (no max tracking / no rescale) and fp16x2 MUFU exp.
// ---------------------------------------------------------------------------

#define L 256
#define D 128
#define NH 4
#define HD 32
#define M_TOTAL (L * L)          // 65536
#define QKV_N (3 * D)            // 384
#define QSCALE 0.17677669529663687f   // 1/sqrt(32)
#define LOG2E 1.4426950408889634f
#define EOFF 8.0f                // e = 2^(s*log2e - EOFF); cancels in o/l

// Scratch
__device__ __half g_zn[(size_t)M_TOTAL * D];
__device__ __half g_qkv[(size_t)M_TOTAL * QKV_N];   // Q pre-scaled
__device__ __half g_o[(size_t)M_TOTAL * D];
__device__ __half g_wq[D * QKV_N];
__device__ __half g_wp[D * D];

// ---- helpers --------------------------------------------------------------
__device__ __forceinline__ uint32_t smem_u32(const void* p) {
    return (uint32_t)__cvta_generic_to_shared(p);
}
__device__ __forceinline__ void ldmx4(uint32_t* r, uint32_t a) {
    asm volatile("ldmatrix.sync.aligned.m8n8.x4.shared.b16 {%0,%1,%2,%3}, [%4];"
                 : "=r"(r[0]), "=r"(r[1]), "=r"(r[2]), "=r"(r[3]) : "r"(a));
}
__device__ __forceinline__ void ldmx4t(uint32_t* r, uint32_t a) {
    asm volatile("ldmatrix.sync.aligned.m8n8.x4.trans.shared.b16 {%0,%1,%2,%3}, [%4];"
                 : "=r"(r[0]), "=r"(r[1]), "=r"(r[2]), "=r"(r[3]) : "r"(a));
}
__device__ __forceinline__ void mma16816(float* d, const uint32_t* a, const uint32_t* b) {
    asm volatile(
        "mma.sync.aligned.m16n8k16.row.col.f32.f16.f16.f32 "
        "{%0,%1,%2,%3}, {%4,%5,%6,%7}, {%8,%9}, {%0,%1,%2,%3};"
        : "+f"(d[0]), "+f"(d[1]), "+f"(d[2]), "+f"(d[3])
        : "r"(a[0]), "r"(a[1]), "r"(a[2]), "r"(a[3]), "r"(b[0]), "r"(b[1]));
}
__device__ __forceinline__ uint32_t packh2(float x, float y) {
    __half2 t = __floats2half2_rn(x, y);
    return *(uint32_t*)&t;
}
__device__ __forceinline__ uint32_t ex2h2(uint32_t p) {
    uint32_t e;
    asm("ex2.approx.f16x2 %0, %1;" : "=r"(e) : "r"(p));
    return e;
}

// ---------------------------------------------------------------------------
// LayerNorm -> zn fp16. One warp per position.
// ---------------------------------------------------------------------------
__global__ void ln_kernel(const float* __restrict__ z,
                          const float* __restrict__ g,
                          const float* __restrict__ b) {
    int pos  = blockIdx.x * 8 + (threadIdx.x >> 5);
    int lane = threadIdx.x & 31;
    const float* zp = z + (size_t)pos * D;

    float4 v = *(const float4*)&zp[lane * 4];
    float s = v.x + v.y + v.z + v.w;
    #pragma unroll
    for (int o = 16; o; o >>= 1) s += __shfl_xor_sync(0xffffffffu, s, o);
    float mu = s * (1.0f / 128.0f);

    float dx = v.x - mu, dy = v.y - mu, dz = v.z - mu, dw = v.w - mu;
    float q = dx * dx + dy * dy + dz * dz + dw * dw;
    #pragma unroll
    for (int o = 16; o; o >>= 1) q += __shfl_xor_sync(0xffffffffu, q, o);
    float rstd = rsqrtf(q * (1.0f / 128.0f) + 1e-5f);

    float4 gg = *(const float4*)&g[lane * 4];
    float4 bb = *(const float4*)&b[lane * 4];
    uint2 o2;
    o2.x = packh2(dx * rstd * gg.x + bb.x, dy * rstd * gg.y + bb.y);
    o2.y = packh2(dz * rstd * gg.z + bb.z, dw * rstd * gg.w + bb.w);
    *(uint2*)&g_zn[(size_t)pos * D + lane * 4] = o2;
}

// ---------------------------------------------------------------------------
// Cast weights to fp16.
// ---------------------------------------------------------------------------
__global__ void castw_kernel(const float* __restrict__ wq,
                             const float* __restrict__ wp) {
    int i = blockIdx.x * 256 + threadIdx.x;
    if (i < D * QKV_N) g_wq[i] = __float2half_rn(wq[i]);
    else {
        int j = i - D * QKV_N;
        if (j < D * D) g_wp[j] = __float2half_rn(wp[j]);
    }
}

// ---------------------------------------------------------------------------
// GEMM: C[M x N] = A[M x 128] @ W[128 x N] (single fp16 pass).
// Block 128x128, 256 threads (2x4 warps, 64x32 warp tile). smem 64 KB.
// Rows 256B = 16 chunks of 16B, swizzle chunk c -> c ^ (row & 7).
// MODE 0: A=g_zn, W=g_wq, C=g_qkv fp16 (+bias, Q cols pre-scaled), N=384
// MODE 1: A=g_o,  W=g_wp, C=out fp32 (+bias +z residual), N=128
// ---------------------------------------------------------------------------
template<int MODE>
__global__ __launch_bounds__(256, 2)
void gemm_kernel(const float* __restrict__ bias,
                 const float* __restrict__ Zr,
                 float* __restrict__ Cout) {
    constexpr int N = (MODE == 0) ? QKV_N : D;
    extern __shared__ char sm_raw[];
    __half* As = (__half*)sm_raw;            // 128x128
    __half* Bs = As + 128 * 128;

    int tid = threadIdx.x;
    int m0 = blockIdx.y * 128;
    int n0 = blockIdx.x * 128;

    const __half* Ag = (MODE == 0) ? g_zn : g_o;
    const __half* Bg = (MODE == 0) ? g_wq : g_wp;

    #pragma unroll
    for (int i = 0; i < 8; i++) {
        int idx = tid + i * 256;
        int m = idx >> 4, c = idx & 15;
        *(uint4*)&As[m * 128 + ((c ^ (m & 7)) * 8)] =
            *(const uint4*)&Ag[(size_t)(m0 + m) * D + c * 8];
    }
    #pragma unroll
    for (int i = 0; i < 8; i++) {
        int idx = tid + i * 256;
        int k = idx >> 4, c = idx & 15;
        *(uint4*)&Bs[k * 128 + ((c ^ (k & 7)) * 8)] =
            *(const uint4*)&Bg[(size_t)k * N + n0 + c * 8];
    }
    __syncthreads();

    int w = tid >> 5, l = tid & 31;
    int mw = (w >> 2) * 64, nw = (w & 3) * 32;
    int sel = l >> 3, li = l & 7;

    uint32_t Abase = smem_u32(As);
    uint32_t Bbase = smem_u32(Bs);

    float acc[4][4][4];
    #pragma unroll
    for (int mt = 0; mt < 4; mt++)
        #pragma unroll
        for (int nt = 0; nt < 4; nt++)
            #pragma unroll
            for (int j = 0; j < 4; j++) acc[mt][nt][j] = 0.0f;

    #pragma unroll
    for (int kt = 0; kt < 8; kt++) {
        uint32_t af[4][4];
        #pragma unroll
        for (int mt = 0; mt < 4; mt++) {
            int m = mw + mt * 16 + li + ((sel & 1) << 3);
            int kc = kt * 2 + (sel >> 1);
            ldmx4(af[mt], Abase + (uint32_t)(m * 128 + ((kc ^ (m & 7)) * 8)) * 2);
        }
        uint32_t bf_[4][2];
        #pragma unroll
        for (int p = 0; p < 2; p++) {
            int k = kt * 16 + ((sel & 1) << 3) + li;
            int nc = (nw >> 3) + p * 2 + (sel >> 1);
            uint32_t t[4];
            ldmx4t(t, Bbase + (uint32_t)(k * 128 + ((nc ^ (k & 7)) * 8)) * 2);
            bf_[2 * p][0] = t[0]; bf_[2 * p][1] = t[1];
            bf_[2 * p + 1][0] = t[2]; bf_[2 * p + 1][1] = t[3];
        }
        #pragma unroll
        for (int mt = 0; mt < 4; mt++)
            #pragma unroll
            for (int nt = 0; nt < 4; nt++)
                mma16816(acc[mt][nt], af[mt], bf_[nt]);
    }

    int grp = l >> 2, qd = l & 3;
    #pragma unroll
    for (int mt = 0; mt < 4; mt++) {
        #pragma unroll
        for (int nt = 0; nt < 4; nt++) {
            int gm = m0 + mw + mt * 16 + grp;
            int gn = n0 + nw + nt * 8 + qd * 2;
            float b0 = bias[gn], b1 = bias[gn + 1];
            float v0 = acc[mt][nt][0] + b0;
            float v1 = acc[mt][nt][1] + b1;
            float v2 = acc[mt][nt][2] + b0;
            float v3 = acc[mt][nt][3] + b1;
            if (MODE == 0) {
                float sc = (gn < D) ? QSCALE : 1.0f;
                *(uint32_t*)&g_qkv[(size_t)gm * N + gn] = packh2(v0 * sc, v1 * sc);
                *(uint32_t*)&g_qkv[(size_t)(gm + 8) * N + gn] = packh2(v2 * sc, v3 * sc);
            } else {
                float2 r0 = *(const float2*)&Zr[(size_t)gm * N + gn];
                float2 r1 = *(const float2*)&Zr[(size_t)(gm + 8) * N + gn];
                *(float2*)&Cout[(size_t)gm * N + gn] = make_float2(v0 + r0.x, v1 + r0.y);
                *(float2*)&Cout[(size_t)(gm + 8) * N + gn] = make_float2(v2 + r1.x, v3 + r1.y);
            }
        }
    }
}

// ---------------------------------------------------------------------------
// Attention: block per (h, r), 256 threads = 8 warps x 32 queries.
// Offset softmax: e = 2^(s*log2e - 8), no max tracking, no rescaling.
// l = plain sum (fp32 accum of per-tile fp16 partial sums), reduced once.
// smem: Q/K/V [256][pitch 40 halves] (80B rows, conflict-free). 60 KB.
// ---------------------------------------------------------------------------
#define APITCH 40
__global__ __launch_bounds__(256, 2)
void attn_kernel() {
    extern __shared__ char sm_raw[];
    __half* Qs = (__half*)sm_raw;            // 256 * 40
    __half* Ks = Qs + 256 * APITCH;
    __half* Vs = Ks + 256 * APITCH;

    int h = blockIdx.x;
    int r = blockIdx.y;
    int tid = threadIdx.x;
    size_t mbase = (size_t)r * L;

    #pragma unroll
    for (int mat = 0; mat < 3; mat++) {
        __half* dst = (mat == 0) ? Qs : (mat == 1) ? Ks : Vs;
        int col0 = mat * D + h * HD;
        #pragma unroll
        for (int i = 0; i < 4; i++) {
            int idx = tid + i * 256;
            int pos = idx >> 2, c = idx & 3;
            *(uint4*)&dst[pos * APITCH + c * 8] =
                *(const uint4*)&g_qkv[(mbase + pos) * QKV_N + col0 + c * 8];
        }
    }
    __syncthreads();

    int w = tid >> 5, l = tid & 31;
    int q0 = w * 32;
    int sel = l >> 3, li = l & 7, grp = l >> 2, qd = l & 3;

    uint32_t Qbase = smem_u32(Qs);
    uint32_t Kbase = smem_u32(Ks);
    uint32_t Vbase = smem_u32(Vs);

    uint32_t qf[2][2][4];
    #pragma unroll
    for (int kk = 0; kk < 2; kk++)
        #pragma unroll
        for (int mt = 0; mt < 2; mt++) {
            int m = q0 + mt * 16 + li + ((sel & 1) << 3);
            int kc = kk * 2 + (sel >> 1);
            ldmx4(qf[kk][mt], Qbase + (uint32_t)(m * APITCH + kc * 8) * 2);
        }

    float lacc[2][2] = {{0.0f, 0.0f}, {0.0f, 0.0f}};   // [mt][row-half]
    float o[2][4][4];
    #pragma unroll
    for (int mt = 0; mt < 2; mt++)
        #pragma unroll
        for (int nt = 0; nt < 4; nt++)
            #pragma unroll
            for (int j = 0; j < 4; j++) o[mt][nt][j] = 0.0f;

    #pragma unroll 1
    for (int t = 0; t < 8; t++) {
        // ---- S = Q K^T (32 x 32) ----
        float s[2][4][4];
        #pragma unroll
        for (int mt = 0; mt < 2; mt++)
            #pragma unroll
            for (int nt = 0; nt < 4; nt++)
                #pragma unroll
                for (int j = 0; j < 4; j++) s[mt][nt][j] = 0.0f;

        #pragma unroll
        for (int kk = 0; kk < 2; kk++) {
            uint32_t kf[4][2];
            #pragma unroll
            for (int p = 0; p < 2; p++) {
                int key = t * 32 + p * 16 + ((sel >> 1) << 3) + li;
                int dc = kk * 2 + (sel & 1);
                uint32_t tr[4];
                ldmx4(tr, Kbase + (uint32_t)(key * APITCH + dc * 8) * 2);
                kf[2 * p][0] = tr[0]; kf[2 * p][1] = tr[1];
                kf[2 * p + 1][0] = tr[2]; kf[2 * p + 1][1] = tr[3];
            }
            #pragma unroll
            for (int mt = 0; mt < 2; mt++)
                #pragma unroll
                for (int nt = 0; nt < 4; nt++)
                    mma16816(s[mt][nt], qf[kk][mt], kf[nt]);
        }

        // ---- P = exp(S) * 2^-EOFF, in fp16 pairs ----
        uint32_t pe[2][4][2];     // [mt][nt][row-half]
        #pragma unroll
        for (int mt = 0; mt < 2; mt++)
            #pragma unroll
            for (int nt = 0; nt < 4; nt++)
                #pragma unroll
                for (int hf = 0; hf < 2; hf++) {
                    float x0 = s[mt][nt][2 * hf] * LOG2E - EOFF;
                    float x1 = s[mt][nt][2 * hf + 1] * LOG2E - EOFF;
                    pe[mt][nt][hf] = ex2h2(packh2(x0, x1));
                }

        // ---- l partial sums (fp16 tree of 4, then fp32 accumulate) ----
        #pragma unroll
        for (int mt = 0; mt < 2; mt++)
            #pragma unroll
            for (int hf = 0; hf < 2; hf++) {
                __half2 a = *(__half2*)&pe[mt][0][hf];
                __half2 b = *(__half2*)&pe[mt][1][hf];
                __half2 c = *(__half2*)&pe[mt][2][hf];
                __half2 d = *(__half2*)&pe[mt][3][hf];
                __half2 sum = __hadd2(__hadd2(a, b), __hadd2(c, d));
                float2 f = __half22float2(sum);
                lacc[mt][hf] += f.x + f.y;
            }

        // ---- O += P V ----
        #pragma unroll
        for (int kt = 0; kt < 2; kt++) {
            uint32_t pa[2][4];
            #pragma unroll
            for (int mt = 0; mt < 2; mt++)
                #pragma unroll
                for (int j = 0; j < 4; j++)
                    pa[mt][j] = pe[mt][2 * kt + (j >> 1)][j & 1];
            uint32_t vf[4][2];
            #pragma unroll
            for (int p = 0; p < 2; p++) {
                int key = t * 32 + kt * 16 + ((sel & 1) << 3) + li;
                int dc = p * 2 + (sel >> 1);
                uint32_t tr[4];
                ldmx4t(tr, Vbase + (uint32_t)(key * APITCH + dc * 8) * 2);
                vf[2 * p][0] = tr[0]; vf[2 * p][1] = tr[1];
                vf[2 * p + 1][0] = tr[2]; vf[2 * p + 1][1] = tr[3];
            }
            #pragma unroll
            for (int mt = 0; mt < 2; mt++)
                #pragma unroll
                for (int nt = 0; nt < 4; nt++)
                    mma16816(o[mt][nt], pa[mt], vf[nt]);
        }
    }

    // ---- reduce l across the quad (cols are spread over lanes qd) ----
    #pragma unroll
    for (int mt = 0; mt < 2; mt++)
        #pragma unroll
        for (int hf = 0; hf < 2; hf++) {
            float v = lacc[mt][hf];
            v += __shfl_xor_sync(0xffffffffu, v, 1);
            v += __shfl_xor_sync(0xffffffffu, v, 2);
            lacc[mt][hf] = v;
        }

    // ---- write O (fp16) ----
    #pragma unroll
    for (int mt = 0; mt < 2; mt++) {
        float inv0 = 1.0f / lacc[mt][0];
        float inv1 = 1.0f / lacc[mt][1];
        #pragma unroll
        for (int nt = 0; nt < 4; nt++) {
            int q = q0 + mt * 16 + grp;
            int d = nt * 8 + qd * 2;
            size_t off0 = (mbase + q) * D + h * HD + d;
            size_t off1 = (mbase + q + 8) * D + h * HD + d;
            *(uint32_t*)&g_o[off0] = packh2(o[mt][nt][0] * inv0, o[mt][nt][1] * inv0);
            *(uint32_t*)&g_o[off1] = packh2(o[mt][nt][2] * inv1, o[mt][nt][3] * inv1);
        }
    }
}

// ---------------------------------------------------------------------------
// Launch
// ---------------------------------------------------------------------------
extern "C" void kernel_launch(void* const* d_in, const int* in_sizes, int n_in,
                              void* d_out, int out_size) {
    const float* z      = (const float*)d_in[0];
    const float* ln_g   = (const float*)d_in[1];
    const float* ln_b   = (const float*)d_in[2];
    const float* w_qkv  = (const float*)d_in[3];
    const float* b_qkv  = (const float*)d_in[4];
    const float* w_proj = (const float*)d_in[5];
    const float* b_proj = (const float*)d_in[6];
    float* out = (float*)d_out;

    const int GEMM_SMEM = 2 * 128 * 128 * 2;       //  65536 B
    const int ATTN_SMEM = 3 * 256 * APITCH * 2;    //  61440 B
    cudaFuncSetAttribute(gemm_kernel<0>,
                         cudaFuncAttributeMaxDynamicSharedMemorySize, GEMM_SMEM);
    cudaFuncSetAttribute(gemm_kernel<1>,
                         cudaFuncAttributeMaxDynamicSharedMemorySize, GEMM_SMEM);
    cudaFuncSetAttribute(attn_kernel,
                         cudaFuncAttributeMaxDynamicSharedMemorySize, ATTN_SMEM);

    ln_kernel<<<M_TOTAL / 8, 256>>>(z, ln_g, ln_b);
    castw_kernel<<<(D * QKV_N + D * D + 255) / 256, 256>>>(w_qkv, w_proj);
    gemm_kernel<0><<<dim3(QKV_N / 128, M_TOTAL / 128), 256, GEMM_SMEM>>>(
        b_qkv, nullptr, nullptr);
    attn_kernel<<<dim3(NH, L), 256, ATTN_SMEM>>>();
    gemm_kernel<1><<<dim3(1, M_TOTAL / 128), 256, GEMM_SMEM>>>(
        b_proj, z, out);
}